// round 4
// baseline (speedup 1.0000x reference)
#include <cuda_runtime.h>

// BinsCombinerLayer: out[b] = (1/NUM_BINS) * sum_{n,s} inputs[b,n,s] * centroids[n,s]
// B=32768, NUM_BINS=16, BIN_SIZE=128. Pure HBM-bound (268 MB stream-once).
//
// R3 lesson: __launch_bounds__(256,8) capped regs at 32, limiting per-warp
// load MLP to ~4-6 -> DRAM request-starved at 81%. This version trades a
// little occupancy (5 blocks/SM, reg budget 51) for a rolling 8-deep
// register load buffer, roughly doubling in-flight bytes per SM.

#define B_TOTAL       32768
#define ROW_FLOATS    2048               // NUM_BINS * BIN_SIZE
#define ROW_VEC4      (ROW_FLOATS / 4)   // 512 float4 per row
#define VEC_PER_LANE  (ROW_VEC4 / 32)    // 16 float4 per lane per example
#define BATCH         8                  // rolling load-buffer depth
#define THREADS       256
#define WARPS_PER_BLOCK (THREADS / 32)
#define BLOCKS_PER_SM 5                  // reg budget 65536/(256*5) = 51
#define GRID_BLOCKS   (148 * BLOCKS_PER_SM)   // 740 persistent blocks
#define INV_NUM_BINS  (1.0f / 16.0f)

__global__ __launch_bounds__(THREADS, BLOCKS_PER_SM)
void bins_combiner_kernel(const float* __restrict__ inputs,
                          const float* __restrict__ centroids,
                          float* __restrict__ out)
{
    __shared__ float4 sc[ROW_VEC4];   // 8 KB centroid table

    const float4* c4 = reinterpret_cast<const float4*>(centroids);
    for (int i = threadIdx.x; i < ROW_VEC4; i += THREADS) {
        sc[i] = c4[i];
    }
    __syncthreads();

    const int warp   = threadIdx.x >> 5;
    const int lane   = threadIdx.x & 31;
    const int gwarp  = blockIdx.x * WARPS_PER_BLOCK + warp;
    const int nwarps = GRID_BLOCKS * WARPS_PER_BLOCK;   // 5920 warps

    for (int b = gwarp; b < B_TOTAL; b += nwarps) {
        const float4* __restrict__ row =
            reinterpret_cast<const float4*>(inputs + (size_t)b * ROW_FLOATS);

        float4 v[BATCH];

        // Prime: issue 8 independent streaming loads (all in flight).
        #pragma unroll
        for (int k = 0; k < BATCH; ++k) {
            v[k] = __ldcs(&row[lane + 32 * k]);
        }

        float acc = 0.0f;

        // Rolling phase: consume v[j], immediately refill with load k=8+j.
        // Keeps ~8 loads outstanding per warp for the whole row.
        #pragma unroll
        for (int j = 0; j < VEC_PER_LANE - BATCH; ++j) {
            float4 w = v[j % BATCH];
            float4 c = sc[lane + 32 * j];
            v[j % BATCH] = __ldcs(&row[lane + 32 * (BATCH + j)]);
            acc += w.x * c.x;
            acc += w.y * c.y;
            acc += w.z * c.z;
            acc += w.w * c.w;
        }

        // Drain the final batch.
        #pragma unroll
        for (int j = VEC_PER_LANE - BATCH; j < VEC_PER_LANE; ++j) {
            float4 w = v[j % BATCH];
            float4 c = sc[lane + 32 * j];
            acc += w.x * c.x;
            acc += w.y * c.y;
            acc += w.z * c.z;
            acc += w.w * c.w;
        }

        // Warp butterfly reduce
        #pragma unroll
        for (int off = 16; off > 0; off >>= 1) {
            acc += __shfl_xor_sync(0xFFFFFFFFu, acc, off);
        }

        if (lane == 0) {
            out[b] = acc * INV_NUM_BINS;
        }
    }
}

extern "C" void kernel_launch(void* const* d_in, const int* in_sizes, int n_in,
                              void* d_out, int out_size)
{
    const float* inputs    = (const float*)d_in[0];   // [32768, 16, 128] f32
    const float* centroids = (const float*)d_in[1];   // [16, 128] f32
    float* out             = (float*)d_out;           // [32768] f32

    bins_combiner_kernel<<<GRID_BLOCKS, THREADS>>>(inputs, centroids, out);
}